// round 2
// baseline (speedup 1.0000x reference)
#include <cuda_runtime.h>
#include <cuda_bf16.h>
#include <cstdint>

#define NLV 127.0f

// ---------------- scratch (__device__ globals) -------------------------------
__device__ float g_maxes[8];                       // 0:x 1:w1 2:w2 3:w3 4:h1 5:h2
__device__ __nv_bfloat16 g_xq[512 * 9216];
__device__ __nv_bfloat16 g_w1q[4096 * 9216];
__device__ __nv_bfloat16 g_w2q[4096 * 4096];
__device__ __nv_bfloat16 g_w3q[1024 * 4096];       // padded 1000 -> 1024 rows
__device__ float g_h[512 * 4096];
__device__ __nv_bfloat16 g_hq[512 * 4096];

// ---------------- helpers ----------------------------------------------------
__device__ __forceinline__ uint32_t smem_u32(const void* p) {
    uint32_t a;
    asm("{ .reg .u64 t; cvta.to.shared.u64 t, %1; cvt.u32.u64 %0, t; }"
        : "=r"(a) : "l"(p));
    return a;
}

__device__ __forceinline__ void cp_async16(uint32_t saddr, const void* g) {
    asm volatile("cp.async.cg.shared.global [%0], [%1], 16;"
                 :: "r"(saddr), "l"(g) : "memory");
}

#define CP_COMMIT() asm volatile("cp.async.commit_group;" ::: "memory")

#define LDSM4(R, addr)                                                          \
    asm volatile("ldmatrix.sync.aligned.m8n8.x4.shared.b16 "                    \
                 "{%0, %1, %2, %3}, [%4];"                                      \
                 : "=r"((R)[0]), "=r"((R)[1]), "=r"((R)[2]), "=r"((R)[3])       \
                 : "r"(addr))

#define MMA16816(C, A, B0, B1)                                                  \
    asm volatile("mma.sync.aligned.m16n8k16.row.col.f32.bf16.bf16.f32 "         \
                 "{%0, %1, %2, %3}, {%4, %5, %6, %7}, {%8, %9}, "               \
                 "{%0, %1, %2, %3};"                                            \
                 : "+f"((C)[0]), "+f"((C)[1]), "+f"((C)[2]), "+f"((C)[3])       \
                 : "r"((A)[0]), "r"((A)[1]), "r"((A)[2]), "r"((A)[3]),          \
                   "r"(B0), "r"(B1))

// ---------------- small kernels ----------------------------------------------
__global__ void init_maxes_kernel() {
    if (threadIdx.x < 8) g_maxes[threadIdx.x] = 0.0f;
}

__global__ void maxabs_kernel(const float* __restrict__ src, int n4, int slot) {
    float m = 0.0f;
    const float4* s4 = (const float4*)src;
    for (int i = blockIdx.x * blockDim.x + threadIdx.x; i < n4;
         i += gridDim.x * blockDim.x) {
        float4 v = s4[i];
        m = fmaxf(m, fmaxf(fmaxf(fabsf(v.x), fabsf(v.y)),
                           fmaxf(fabsf(v.z), fabsf(v.w))));
    }
#pragma unroll
    for (int o = 16; o; o >>= 1) m = fmaxf(m, __shfl_xor_sync(0xFFFFFFFFu, m, o));
    __shared__ float sm[8];
    if ((threadIdx.x & 31) == 0) sm[threadIdx.x >> 5] = m;
    __syncthreads();
    if (threadIdx.x == 0) {
        float mm = sm[0];
#pragma unroll
        for (int w = 1; w < 8; w++) mm = fmaxf(mm, sm[w]);
        atomicMax((unsigned int*)&g_maxes[slot], __float_as_uint(mm));
    }
}

__device__ __forceinline__ uint32_t pack_bf16x2(float a, float b) {
    uint32_t lo = (uint32_t)__bfloat16_as_ushort(__float2bfloat16_rn(a));
    uint32_t hi = (uint32_t)__bfloat16_as_ushort(__float2bfloat16_rn(b));
    return lo | (hi << 16);
}

// quantize fp32 -> integer-valued bf16 (round-half-even, clip [lo,127])
__global__ void quant_kernel(const float* __restrict__ src,
                             __nv_bfloat16* __restrict__ dst,
                             int n4, int npad4, int slot, float lo) {
    float mx = g_maxes[slot];
    float scale = mx / NLV;
    if (!(scale > 0.0f)) scale = 1.0f;
    float inv = 1.0f / scale;
    for (int i = blockIdx.x * blockDim.x + threadIdx.x; i < npad4;
         i += gridDim.x * blockDim.x) {
        uint32_t w0 = 0u, w1 = 0u;
        if (i < n4) {
            float4 v = ((const float4*)src)[i];
            float q0 = fminf(fmaxf(rintf(v.x * inv), lo), NLV);
            float q1 = fminf(fmaxf(rintf(v.y * inv), lo), NLV);
            float q2 = fminf(fmaxf(rintf(v.z * inv), lo), NLV);
            float q3 = fminf(fmaxf(rintf(v.w * inv), lo), NLV);
            w0 = pack_bf16x2(q0, q1);
            w1 = pack_bf16x2(q2, q3);
        }
        ((uint2*)dst)[i] = make_uint2(w0, w1);
    }
}

// ---------------- HMMA GEMM ---------------------------------------------------
// C[M=512, Nout] = A[512,K] @ B[Npad,K]^T, bf16 in (integer-valued), fp32 accum.
// Tile 128x128x64, 3-stage cp.async pipeline, 8 warps (64x32 warp tiles).
// Epilogue: dequant (sa*sw), quantized bias, optional ReLU, fused abs-max.
constexpr int BM = 128, BN = 128, BK = 64, STAGES = 3, NTHREADS = 256;
constexpr int STAGE_BYTES = (BM * BK + BN * BK) * 2;   // 32768
constexpr int B_OFS = BM * BK * 2;                     // 16384

__global__ void __launch_bounds__(NTHREADS, 1)
gemm_q_kernel(const __nv_bfloat16* __restrict__ A,
              const __nv_bfloat16* __restrict__ B,
              const float* __restrict__ bias, float* __restrict__ out,
              int K, int Nout, int relu, int maxslot, int sa_slot, int sw_slot) {
    extern __shared__ char smem_raw[];
    const uint32_t sb = smem_u32(smem_raw);

    const int tid = threadIdx.x;
    const int lane = tid & 31;
    const int wid = tid >> 5;
    const int wm = wid & 1;        // 2 m-blocks of 64
    const int wn = wid >> 1;       // 4 n-blocks of 32
    const int m0 = blockIdx.y * BM;
    const int n0 = blockIdx.x * BN;

    // ---- global->shared mapping: 2048 x 16B chunks / 256 threads = 8 each ----
    uint32_t s_st[8];
    const __nv_bfloat16* g_st[8];
#pragma unroll
    for (int i = 0; i < 8; i++) {
        int li = i * NTHREADS + tid;
        int isA = (li < 1024);
        int idx = li & 1023;
        int row = idx >> 3;            // 0..127
        int c = idx & 7;               // 16B chunk within 128B row
        s_st[i] = (uint32_t)((isA ? 0 : B_OFS) + row * 128 +
                             ((c ^ (row & 7)) << 4));
        g_st[i] = (isA ? (A + (size_t)(m0 + row) * K)
                       : (B + (size_t)(n0 + row) * K)) + c * 8;
    }

    const int NK = K >> 6;

    // prologue loads
#pragma unroll
    for (int st = 0; st < 2; st++) {
        if (st < NK) {
            uint32_t base = sb + (uint32_t)(st % STAGES) * STAGE_BYTES;
#pragma unroll
            for (int i = 0; i < 8; i++)
                cp_async16(base + s_st[i], g_st[i] + (size_t)st * BK);
            CP_COMMIT();
        }
    }

    // ---- ldmatrix per-lane base addresses (within stage) ----
    const int r = lane & 7;
    const int g = lane >> 3;
    // A: row = wm*64 + mi*16 + (g&1)*8 + r, chunk = 2s + (g>>1)
    uint32_t a_row[4];
    int a_rx[4];
#pragma unroll
    for (int mi = 0; mi < 4; mi++) {
        int row = wm * 64 + mi * 16 + (g & 1) * 8 + r;
        a_row[mi] = (uint32_t)(row * 128);
        a_rx[mi] = row & 7;
    }
    // B: row = wn*32 + p*16 + (g>>1)*8 + r, chunk = 2s + (g&1)
    uint32_t b_row[2];
    int b_rx[2];
#pragma unroll
    for (int p = 0; p < 2; p++) {
        int row = wn * 32 + p * 16 + (g >> 1) * 8 + r;
        b_row[p] = (uint32_t)(B_OFS + row * 128);
        b_rx[p] = row & 7;
    }

    float acc[4][4][4];
#pragma unroll
    for (int mi = 0; mi < 4; mi++)
#pragma unroll
        for (int ni = 0; ni < 4; ni++)
#pragma unroll
            for (int e = 0; e < 4; e++) acc[mi][ni][e] = 0.0f;

#pragma unroll 1
    for (int kc = 0; kc < NK; kc++) {
        if (kc + 2 < NK) {
            uint32_t base = sb + (uint32_t)((kc + 2) % STAGES) * STAGE_BYTES;
#pragma unroll
            for (int i = 0; i < 8; i++)
                cp_async16(base + s_st[i], g_st[i] + (size_t)(kc + 2) * BK);
            CP_COMMIT();
        }
        int rem = NK - 1 - kc;
        if (rem >= 2)      asm volatile("cp.async.wait_group 2;" ::: "memory");
        else if (rem == 1) asm volatile("cp.async.wait_group 1;" ::: "memory");
        else               asm volatile("cp.async.wait_group 0;" ::: "memory");
        __syncthreads();

        const uint32_t stage = sb + (uint32_t)(kc % STAGES) * STAGE_BYTES;
#pragma unroll
        for (int s = 0; s < 4; s++) {
            uint32_t af[4][4];
#pragma unroll
            for (int mi = 0; mi < 4; mi++) {
                int chunk = 2 * s + (g >> 1);
                LDSM4(af[mi], stage + a_row[mi] +
                              (uint32_t)((chunk ^ a_rx[mi]) << 4));
            }
            uint32_t bf[2][4];
#pragma unroll
            for (int p = 0; p < 2; p++) {
                int chunk = 2 * s + (g & 1);
                LDSM4(bf[p], stage + b_row[p] +
                             (uint32_t)((chunk ^ b_rx[p]) << 4));
            }
#pragma unroll
            for (int mi = 0; mi < 4; mi++) {
#pragma unroll
                for (int p = 0; p < 2; p++) {
                    MMA16816(acc[mi][2 * p],     af[mi], bf[p][0], bf[p][1]);
                    MMA16816(acc[mi][2 * p + 1], af[mi], bf[p][2], bf[p][3]);
                }
            }
        }
        __syncthreads();
    }

    // ---- epilogue: dequant + quantized bias + relu + fused abs-max ----
    const float sa = g_maxes[sa_slot] / NLV;
    const float sw = g_maxes[sw_slot] / NLV;
    const float bs = sa * sw;
    float lmax = 0.0f;

    // per-(ni) bias (depends only on n)
    float bq[4][2];
#pragma unroll
    for (int ni = 0; ni < 4; ni++) {
        int n = n0 + wn * 32 + ni * 8 + (lane & 3) * 2;
#pragma unroll
        for (int e = 0; e < 2; e++) {
            bq[ni][e] = (n + e < Nout) ? rintf(bias[n + e] / bs) * bs : 0.0f;
        }
    }

#pragma unroll
    for (int mi = 0; mi < 4; mi++) {
#pragma unroll
        for (int half = 0; half < 2; half++) {
            int m = m0 + wm * 64 + mi * 16 + (lane >> 2) + half * 8;
#pragma unroll
            for (int ni = 0; ni < 4; ni++) {
                int n = n0 + wn * 32 + ni * 8 + (lane & 3) * 2;
                if (n < Nout) {
                    float v0 = acc[mi][ni][half * 2 + 0] * bs + bq[ni][0];
                    float v1 = acc[mi][ni][half * 2 + 1] * bs + bq[ni][1];
                    if (relu) { v0 = fmaxf(v0, 0.0f); v1 = fmaxf(v1, 0.0f); }
                    float2 vv = make_float2(v0, v1);
                    *(float2*)(out + (size_t)m * Nout + n) = vv;
                    lmax = fmaxf(lmax, fmaxf(fabsf(v0), fabsf(v1)));
                }
            }
        }
    }
    if (maxslot >= 0) {
#pragma unroll
        for (int o = 16; o; o >>= 1)
            lmax = fmaxf(lmax, __shfl_xor_sync(0xFFFFFFFFu, lmax, o));
        if (lane == 0)
            atomicMax((unsigned int*)&g_maxes[maxslot], __float_as_uint(lmax));
    }
}

// ---------------- launch -------------------------------------------------------
extern "C" void kernel_launch(void* const* d_in, const int* in_sizes, int n_in,
                              void* d_out, int out_size) {
    const float* x  = (const float*)d_in[0];
    const float* w1 = (const float*)d_in[1];
    const float* b1 = (const float*)d_in[2];
    const float* w2 = (const float*)d_in[3];
    const float* b2 = (const float*)d_in[4];
    const float* w3 = (const float*)d_in[5];
    const float* b3 = (const float*)d_in[6];
    float* out = (float*)d_out;

    void *p_xq, *p_w1q, *p_w2q, *p_w3q, *p_h, *p_hq;
    cudaGetSymbolAddress(&p_xq, g_xq);
    cudaGetSymbolAddress(&p_w1q, g_w1q);
    cudaGetSymbolAddress(&p_w2q, g_w2q);
    cudaGetSymbolAddress(&p_w3q, g_w3q);
    cudaGetSymbolAddress(&p_h, g_h);
    cudaGetSymbolAddress(&p_hq, g_hq);

    const int SMEM = STAGES * STAGE_BYTES;   // 98304
    cudaFuncSetAttribute(gemm_q_kernel,
                         cudaFuncAttributeMaxDynamicSharedMemorySize, SMEM);

    const int RB = 1184;  // 8 * 148 SMs, grid-stride

    init_maxes_kernel<<<1, 32>>>();
    maxabs_kernel<<<RB, 256>>>(x,  (512 * 9216) / 4, 0);
    maxabs_kernel<<<RB, 256>>>(w1, (4096 * 9216) / 4, 1);
    maxabs_kernel<<<RB, 256>>>(w2, (4096 * 4096) / 4, 2);
    maxabs_kernel<<<RB, 256>>>(w3, (1000 * 4096) / 4, 3);

    quant_kernel<<<RB, 256>>>(x,  (__nv_bfloat16*)p_xq,
                              (512 * 9216) / 4, (512 * 9216) / 4, 0, -128.0f);
    quant_kernel<<<RB, 256>>>(w1, (__nv_bfloat16*)p_w1q,
                              (4096 * 9216) / 4, (4096 * 9216) / 4, 1, -127.0f);
    quant_kernel<<<RB, 256>>>(w2, (__nv_bfloat16*)p_w2q,
                              (4096 * 4096) / 4, (4096 * 4096) / 4, 2, -127.0f);
    quant_kernel<<<RB, 256>>>(w3, (__nv_bfloat16*)p_w3q,
                              (1000 * 4096) / 4, (1024 * 4096) / 4, 3, -127.0f);

    // Layer 1: h = relu(xq @ w1q^T * s + bq), fused max -> slot 4
    gemm_q_kernel<<<dim3(32, 4), NTHREADS, SMEM>>>(
        (const __nv_bfloat16*)p_xq, (const __nv_bfloat16*)p_w1q, b1,
        (float*)p_h, 9216, 4096, 1, 4, 0, 1);
    quant_kernel<<<RB, 256>>>((const float*)p_h, (__nv_bfloat16*)p_hq,
                              (512 * 4096) / 4, (512 * 4096) / 4, 4, -128.0f);

    // Layer 2
    gemm_q_kernel<<<dim3(32, 4), NTHREADS, SMEM>>>(
        (const __nv_bfloat16*)p_hq, (const __nv_bfloat16*)p_w2q, b2,
        (float*)p_h, 4096, 4096, 1, 5, 4, 2);
    quant_kernel<<<RB, 256>>>((const float*)p_h, (__nv_bfloat16*)p_hq,
                              (512 * 4096) / 4, (512 * 4096) / 4, 5, -128.0f);

    // Layer 3 -> d_out (N=1000, weights padded to 1024 rows with zeros)
    gemm_q_kernel<<<dim3(8, 4), NTHREADS, SMEM>>>(
        (const __nv_bfloat16*)p_hq, (const __nv_bfloat16*)p_w3q, b3,
        out, 4096, 1000, 0, -1, 5, 3);
}